// round 12
// baseline (speedup 1.0000x reference)
#include <cuda_runtime.h>
#include <cuda_bf16.h>
#include <cstdint>

// ---------------------------------------------------------------------------
// BarbershopTransformer: 6-layer GPT forward, B=32 T=256 C=384 H=6 D=64 V=32000
// Round 9: cp.async double-buffered tf32 GEMM (BK=16, 2 stages), weights
// pre-rounded to tf32 at staging, activations rounded at producer stores,
// fused QKV GEMM via packed weight.
// ---------------------------------------------------------------------------

#define NL    6
#define C     384
#define HN    6
#define HD    64
#define TT    256
#define BB    32
#define M_TOK (BB*TT)          // 8192
#define FF    (4*C)            // 1536
#define V     32000
#define C3    (3*C)            // 1152

__device__ float g_x   [M_TOK*C];
__device__ float g_h   [M_TOK*C];
__device__ float g_att [M_TOK*C];
__device__ float g_mlp [M_TOK*FF];
__device__ float g_qkvb[M_TOK*C3];

#define WBUF_ORIG 35349248
#define WBUF_TOTAL (WBUF_ORIG + NL*C*C3)
__device__ float g_wbuf[WBUF_TOTAL];
__device__ int   g_in_bf16;
__device__ int   g_out_bf16;

__device__ __forceinline__ float* buf_sel(int s) {
    switch (s) {
        case 0: return g_x;
        case 1: return g_h;
        case 5: return g_att;
        case 6: return g_mlp;
        default: return g_qkvb;   // 7
    }
}

// ---------------------------------------------------------------------------
__device__ __forceinline__ float tf32r(float x) {
    float y;
    asm("cvt.rna.tf32.f32 %0, %1;" : "=f"(y) : "f"(x));
    return y;
}

__global__ void flags_kernel(const void* buf, int in_mode, int out_mode) {
    __shared__ int sh;
    int tid = threadIdx.x;
    if (tid == 0) sh = 0;
    __syncthreads();
    if (in_mode < 0) {
        const __nv_bfloat16* s = (const __nv_bfloat16*)buf;
        int cnt = 0;
        for (int i = tid; i < 4096; i += 256) {
            float f = __bfloat162float(s[i]);
            if (!isfinite(f) || fabsf(f) > 8.0f) cnt++;
        }
        atomicAdd(&sh, cnt);
    }
    __syncthreads();
    if (tid == 0) {
        int in_bf16 = (in_mode < 0) ? ((sh > 64) ? 0 : 1) : in_mode;
        g_in_bf16  = in_bf16;
        g_out_bf16 = (out_mode < 0) ? in_bf16 : out_mode;
    }
}

// Stage one tensor to f32 (optionally pre-rounded to tf32 for GEMM B operands).
__global__ void convert_kernel(const void* src, long long off, int n, int rnd) {
    int i = blockIdx.x * blockDim.x + threadIdx.x;
    if (i >= n) return;
    float vv;
    if (g_in_bf16) vv = __bfloat162float(((const __nv_bfloat16*)src)[i]);
    else           vv = ((const float*)src)[i];
    if (rnd) vv = tf32r(vv);
    long long o = off + i;
    if (o >= 0 && o < WBUF_TOTAL) g_wbuf[o] = vv;
}

// Pack Wq|Wk|Wv -> [NL][C][3C]
__global__ void pack_qkv(long long oWq, long long oWk, long long oWv, long long dst) {
    int i = blockIdx.x * blockDim.x + threadIdx.x;
    if (i >= NL * C * C3) return;
    int n3  = i % C3;
    int rem = i / C3;          // l*C + k
    int part = n3 / C, n = n3 % C;
    long long src = (part == 0 ? oWq : part == 1 ? oWk : oWv) + (long long)rem * C + n;
    g_wbuf[dst + i] = g_wbuf[src];
}

// ---------------------------------------------------------------------------
__global__ void embed_kernel(const int* __restrict__ idx,
                             long long tokOff, long long posOff) {
    int m = blockIdx.x;
    int c = threadIdx.x;
    int t = m & (TT - 1);
    int tk = idx[m];
    if ((unsigned)tk >= (unsigned)V) tk = 0;
    const float* tok = g_wbuf + tokOff;
    const float* pos = g_wbuf + posOff;
    g_x[m * C + c] = tok[tk * C + c] + pos[t * C + c];
}

// ---------------------------------------------------------------------------
// LayerNorm; output optionally tf32-rounded (it is only ever a GEMM A input).
__global__ void ln_kernel(int inSel, long long gOff, long long bOff, int outSel,
                          int rnd) {
    __shared__ float red[4];
    __shared__ float stat[2];
    const float* x = buf_sel(inSel);
    float* out     = buf_sel(outSel);
    const float* g = g_wbuf + gOff;
    const float* b = g_wbuf + bOff;
    int row = blockIdx.x, tid = threadIdx.x;
    const float* xr = x + (size_t)row * C;
    float v0 = xr[tid], v1 = xr[tid + 128], v2 = xr[tid + 256];
    float s = v0 + v1 + v2;
    #pragma unroll
    for (int o = 16; o; o >>= 1) s += __shfl_xor_sync(0xffffffffu, s, o);
    if ((tid & 31) == 0) red[tid >> 5] = s;
    __syncthreads();
    if (tid == 0) stat[0] = (red[0] + red[1] + red[2] + red[3]) * (1.0f / C);
    __syncthreads();
    float m = stat[0];
    float d0 = v0 - m, d1 = v1 - m, d2 = v2 - m;
    float q = d0 * d0 + d1 * d1 + d2 * d2;
    #pragma unroll
    for (int o = 16; o; o >>= 1) q += __shfl_xor_sync(0xffffffffu, q, o);
    if ((tid & 31) == 0) red[tid >> 5] = q;
    __syncthreads();
    if (tid == 0)
        stat[1] = rsqrtf((red[0] + red[1] + red[2] + red[3]) * (1.0f / C) + 1e-5f);
    __syncthreads();
    float r = stat[1];
    float* o = out + (size_t)row * C;
    float o0 = d0 * r * g[tid]       + b[tid];
    float o1 = d1 * r * g[tid + 128] + b[tid + 128];
    float o2 = d2 * r * g[tid + 256] + b[tid + 256];
    if (rnd) { o0 = tf32r(o0); o1 = tf32r(o1); o2 = tf32r(o2); }
    o[tid] = o0; o[tid + 128] = o1; o[tid + 256] = o2;
}

// ---------------------------------------------------------------------------
__device__ __forceinline__ void mma_tf32(float& c0, float& c1, float& c2, float& c3,
                                         uint32_t a0, uint32_t a1, uint32_t a2, uint32_t a3,
                                         uint32_t b0, uint32_t b1) {
    asm volatile(
        "mma.sync.aligned.m16n8k8.row.col.f32.tf32.tf32.f32 "
        "{%0,%1,%2,%3}, {%4,%5,%6,%7}, {%8,%9}, {%0,%1,%2,%3};\n"
        : "+f"(c0), "+f"(c1), "+f"(c2), "+f"(c3)
        : "r"(a0), "r"(a1), "r"(a2), "r"(a3), "r"(b0), "r"(b1));
}
__device__ __forceinline__ void cp16(uint32_t s, const void* g) {
    asm volatile("cp.async.cg.shared.global [%0], [%1], 16;" :: "r"(s), "l"(g));
}

// ---------------------------------------------------------------------------
// Double-buffered tf32 GEMM: C[M,N] = A[M,K] @ B[K,N]. BM=BN=128, BK=16,
// 2 cp.async stages, 256 thr (8 warps of 64x32). Inputs already tf32-rounded.
#define ASTR 20
#define BSTR 132
template<bool BIAS, bool RELU, bool RES, bool ROUND, bool DYNOUT>
__global__ void __launch_bounds__(256, 2)
mma_gemm(int aSel, long long bOff, long long biasOff,
         int outSel, void* dOutPtr, int M, int N, int K, int Mlim) {
    __shared__ float As[2][128 * ASTR];   // 20480 B
    __shared__ float Bs[2][16 * BSTR];    // 16896 B
    const float* A  = buf_sel(aSel);
    const float* B  = g_wbuf + bOff;
    const float* bi = g_wbuf + biasOff;

    int tid = threadIdx.x;
    int warp = tid >> 5, lane = tid & 31;
    int wm = warp >> 2;
    int wn = warp & 3;
    int g = lane >> 2, t = lane & 3;
    int bm = blockIdx.y * 128, bn = blockIdx.x * 128;

    uint32_t aSm[2], bSm[2];
    aSm[0] = (uint32_t)__cvta_generic_to_shared(&As[0][0]);
    aSm[1] = (uint32_t)__cvta_generic_to_shared(&As[1][0]);
    bSm[0] = (uint32_t)__cvta_generic_to_shared(&Bs[0][0]);
    bSm[1] = (uint32_t)__cvta_generic_to_shared(&Bs[1][0]);

    // per-thread chunk coords (2 chunks each for A and B per stage)
    int ar[2], ak[2], br[2], bnc[2];
    #pragma unroll
    for (int u = 0; u < 2; u++) {
        int f = tid + u * 256;        // 0..511
        ar[u] = f >> 2; ak[u] = (f & 3) * 4;
        br[u] = f >> 5; bnc[u] = (f & 31) * 4;
    }

    float acc[4][4][4];
    #pragma unroll
    for (int mi = 0; mi < 4; mi++)
        #pragma unroll
        for (int ni = 0; ni < 4; ni++)
            #pragma unroll
            for (int cc = 0; cc < 4; cc++) acc[mi][ni][cc] = 0.f;

    int niter = K >> 4;

    // prologue: stage 0
    {
        #pragma unroll
        for (int u = 0; u < 2; u++) {
            cp16(aSm[0] + (uint32_t)(ar[u] * ASTR + ak[u]) * 4,
                 A + (size_t)(bm + ar[u]) * K + ak[u]);
            cp16(bSm[0] + (uint32_t)(br[u] * BSTR + bnc[u]) * 4,
                 B + (size_t)br[u] * N + bn + bnc[u]);
        }
        asm volatile("cp.async.commit_group;");
    }

    for (int i = 0; i < niter; i++) {
        int cur = i & 1;
        if (i + 1 < niter) {
            int nxt = cur ^ 1;
            int k0n = (i + 1) << 4;
            #pragma unroll
            for (int u = 0; u < 2; u++) {
                cp16(aSm[nxt] + (uint32_t)(ar[u] * ASTR + ak[u]) * 4,
                     A + (size_t)(bm + ar[u]) * K + k0n + ak[u]);
                cp16(bSm[nxt] + (uint32_t)(br[u] * BSTR + bnc[u]) * 4,
                     B + (size_t)(k0n + br[u]) * N + bn + bnc[u]);
            }
            asm volatile("cp.async.commit_group;");
            asm volatile("cp.async.wait_group 1;");
        } else {
            asm volatile("cp.async.wait_group 0;");
        }
        __syncthreads();

        const uint32_t* Asu = (const uint32_t*)As[cur];
        const uint32_t* Bsu = (const uint32_t*)Bs[cur];
        #pragma unroll
        for (int kk = 0; kk < 16; kk += 8) {
            uint32_t af[4][4];
            #pragma unroll
            for (int mi = 0; mi < 4; mi++) {
                int row = wm * 64 + mi * 16;
                af[mi][0] = Asu[(row + g)     * ASTR + kk + t];
                af[mi][1] = Asu[(row + g + 8) * ASTR + kk + t];
                af[mi][2] = Asu[(row + g)     * ASTR + kk + t + 4];
                af[mi][3] = Asu[(row + g + 8) * ASTR + kk + t + 4];
            }
            uint32_t bf[4][2];
            #pragma unroll
            for (int ni = 0; ni < 4; ni++) {
                int col = wn * 32 + ni * 8 + g;
                bf[ni][0] = Bsu[(kk + t)     * BSTR + col];
                bf[ni][1] = Bsu[(kk + t + 4) * BSTR + col];
            }
            #pragma unroll
            for (int mi = 0; mi < 4; mi++)
                #pragma unroll
                for (int ni = 0; ni < 4; ni++)
                    mma_tf32(acc[mi][ni][0], acc[mi][ni][1],
                             acc[mi][ni][2], acc[mi][ni][3],
                             af[mi][0], af[mi][1], af[mi][2], af[mi][3],
                             bf[ni][0], bf[ni][1]);
        }
        __syncthreads();
    }

    // epilogue
    bool store_bf16 = DYNOUT ? (g_out_bf16 != 0) : false;
    float* outBuf = DYNOUT ? nullptr : buf_sel(outSel);
    #pragma unroll
    for (int mi = 0; mi < 4; mi++) {
        #pragma unroll
        for (int ni = 0; ni < 4; ni++) {
            int col = bn + wn * 32 + ni * 8 + t * 2;
            float b0 = 0.f, b1 = 0.f;
            if (BIAS) { b0 = bi[col]; b1 = bi[col + 1]; }
            #pragma unroll
            for (int half = 0; half < 2; half++) {
                int row = bm + wm * 64 + mi * 16 + g + half * 8;
                if (row >= Mlim) continue;
                float v0 = acc[mi][ni][half * 2 + 0];
                float v1 = acc[mi][ni][half * 2 + 1];
                if (BIAS) { v0 += b0; v1 += b1; }
                if (RELU) { v0 = fmaxf(v0, 0.f); v1 = fmaxf(v1, 0.f); }
                long long base = (long long)row * N + col;
                if (RES) {
                    float2 rr = *(const float2*)(g_x + base);
                    v0 += rr.x; v1 += rr.y;
                }
                if (ROUND) { v0 = tf32r(v0); v1 = tf32r(v1); }
                if (DYNOUT) {
                    if (store_bf16) {
                        __nv_bfloat162 pk = __floats2bfloat162_rn(v0, v1);
                        *(__nv_bfloat162*)((__nv_bfloat16*)dOutPtr + base) = pk;
                    } else {
                        *(float2*)((float*)dOutPtr + base) = make_float2(v0, v1);
                    }
                } else {
                    *(float2*)(outBuf + base) = make_float2(v0, v1);
                }
            }
        }
    }
}

// ---------------------------------------------------------------------------
// Flash attention on the fused qkv buffer [M, 1152]: q|k|v at col 0/384/768.
// Block = (b,h,qtile of 32), 8 warps x 4 queries. Output tf32-rounded.
#define KSTR 65
#define QS   C3
__global__ void __launch_bounds__(256)
flash_attn() {
    __shared__ float Ks[64 * KSTR];
    __shared__ float Vs[64 * 64];
    __shared__ float Ps[8][4][64];
    int blk = blockIdx.x;
    int qt = blk & 7;
    int bh = blk >> 3;
    int b = bh / HN, h = bh % HN;
    int tid = threadIdx.x, w = tid >> 5, lane = tid & 31;
    int qbase = qt * 32 + w * 4;
    const float scale = rsqrtf((float)C);

    float q[4][2];
    #pragma unroll
    for (int qi = 0; qi < 4; qi++) {
        long long base = (long long)(b * TT + qbase + qi) * QS + h * HD;
        q[qi][0] = g_qkvb[base + lane]      * scale;
        q[qi][1] = g_qkvb[base + lane + 32] * scale;
    }
    float o[4][2];
    float m[4], l[4];
    #pragma unroll
    for (int qi = 0; qi < 4; qi++) {
        o[qi][0] = o[qi][1] = 0.f;
        m[qi] = -1e30f; l[qi] = 0.f;
    }

    int nch = (qt * 32 + 31) / 64 + 1;
    for (int c = 0; c < nch; c++) {
        __syncthreads();
        #pragma unroll
        for (int u = 0; u < 4; u++) {
            int f = tid + u * 256;
            int r = f >> 4, dc = (f & 15) * 4;
            long long gb = (long long)(b * TT + c * 64 + r) * QS + h * HD + dc;
            float4 kv = *(const float4*)(g_qkvb + gb + C);
            Ks[r * KSTR + dc]     = kv.x;
            Ks[r * KSTR + dc + 1] = kv.y;
            Ks[r * KSTR + dc + 2] = kv.z;
            Ks[r * KSTR + dc + 3] = kv.w;
            float4 vv = *(const float4*)(g_qkvb + gb + 2 * C);
            *(float4*)(Vs + r * 64 + dc) = vv;
        }
        __syncthreads();

        float sc[4][2];
        #pragma unroll
        for (int qi = 0; qi < 4; qi++) { sc[qi][0] = 0.f; sc[qi][1] = 0.f; }
        #pragma unroll 8
        for (int d = 0; d < 32; d++) {
            float k0 = Ks[lane * KSTR + d];
            float k1 = Ks[(lane + 32) * KSTR + d];
            #pragma unroll
            for (int qi = 0; qi < 4; qi++) {
                float qd = __shfl_sync(0xffffffffu, q[qi][0], d);
                sc[qi][0] = fmaf(qd, k0, sc[qi][0]);
                sc[qi][1] = fmaf(qd, k1, sc[qi][1]);
            }
        }
        #pragma unroll 8
        for (int d = 0; d < 32; d++) {
            float k0 = Ks[lane * KSTR + 32 + d];
            float k1 = Ks[(lane + 32) * KSTR + 32 + d];
            #pragma unroll
            for (int qi = 0; qi < 4; qi++) {
                float qd = __shfl_sync(0xffffffffu, q[qi][1], d);
                sc[qi][0] = fmaf(qd, k0, sc[qi][0]);
                sc[qi][1] = fmaf(qd, k1, sc[qi][1]);
            }
        }

        int s0 = c * 64 + lane, s1 = s0 + 32;
        #pragma unroll
        for (int qi = 0; qi < 4; qi++) {
            int tq = qbase + qi;
            float a0 = (s0 <= tq) ? sc[qi][0] : -1e30f;
            float a1 = (s1 <= tq) ? sc[qi][1] : -1e30f;
            float cm = fmaxf(a0, a1);
            #pragma unroll
            for (int off = 16; off; off >>= 1)
                cm = fmaxf(cm, __shfl_xor_sync(0xffffffffu, cm, off));
            float nm = fmaxf(m[qi], cm);
            float fac = __expf(m[qi] - nm);
            float p0 = __expf(a0 - nm);
            float p1 = __expf(a1 - nm);
            float ps = p0 + p1;
            #pragma unroll
            for (int off = 16; off; off >>= 1)
                ps += __shfl_xor_sync(0xffffffffu, ps, off);
            m[qi] = nm;
            l[qi] = l[qi] * fac + ps;
            o[qi][0] *= fac; o[qi][1] *= fac;
            Ps[w][qi][lane]      = p0;
            Ps[w][qi][lane + 32] = p1;
        }
        __syncwarp();
        #pragma unroll 4
        for (int s = 0; s < 64; s++) {
            float v0 = Vs[s * 64 + lane];
            float v1 = Vs[s * 64 + lane + 32];
            #pragma unroll
            for (int qi = 0; qi < 4; qi++) {
                float pv = Ps[w][qi][s];
                o[qi][0] = fmaf(pv, v0, o[qi][0]);
                o[qi][1] = fmaf(pv, v1, o[qi][1]);
            }
        }
    }

    #pragma unroll
    for (int qi = 0; qi < 4; qi++) {
        float inv = 1.f / l[qi];
        long long base = (long long)(b * TT + qbase + qi) * C + h * HD;
        g_att[base + lane]      = tf32r(o[qi][0] * inv);
        g_att[base + lane + 32] = tf32r(o[qi][1] * inv);
    }
}

// ---------------------------------------------------------------------------
static const int SIG_E[20] = {
    8192, 12288000, 98304, 2304, 2304, 884736, 884736, 884736, 884736, 2304,
    2304, 2304, 3538944, 9216, 3538944, 2304, 384, 384, 12288000, 32000};
static const int ALPHA_E[20] = {
    9216, 2304, 8192, 32000, 12288000, 2304, 2304, 2304, 2304, 384, 384,
    98304, 12288000, 3538944, 3538944, 884736, 884736, 2304, 884736, 884736};
static const int ALPHA_TO_SIG[20] = {
    13, 15, 0, 19, 18, 4, 3, 11, 10, 17, 16, 2, 1, 12, 14, 6, 8, 9, 5, 7};
static const int ALPHA_IDX_POS = 2;
static const int FSIZES[19] = {
    12288000, 98304, 2304, 2304, 884736, 884736, 884736, 884736, 2304,
    2304, 2304, 3538944, 9216, 3538944, 2304, 384, 384, 12288000, 32000};
// pre-round to tf32: wq wk wv wo w1 w2 lm_w
static const int FROUND[19] = {
    0, 0, 0, 0, 1, 1, 1, 1, 0, 0, 0, 1, 0, 1, 0, 0, 0, 1, 0};

static bool match_pat(const int* s, const int* E, int idx_pos,
                      int fmult, int idx_mult) {
    for (int i = 0; i < 20; i++) {
        long long expect = (long long)E[i] * ((i == idx_pos) ? idx_mult : fmult);
        if ((long long)s[i] != expect) return false;
    }
    return true;
}

extern "C" void kernel_launch(void* const* d_in, const int* in_sizes, int n_in,
                              void* d_out, int out_size) {
    if (n_in != 20) return;

    int in_mode = -2;
    bool alpha = false;
    if      (match_pat(in_sizes, SIG_E,   0,             1, 1)) { in_mode = -1; }
    else if (match_pat(in_sizes, ALPHA_E, ALPHA_IDX_POS, 1, 1)) { in_mode = -1; alpha = true; }
    else if (match_pat(in_sizes, SIG_E,   0,             4, 4)) { in_mode = 0; }
    else if (match_pat(in_sizes, ALPHA_E, ALPHA_IDX_POS, 4, 4)) { in_mode = 0; alpha = true; }
    else if (match_pat(in_sizes, SIG_E,   0,             2, 4)) { in_mode = 1; }
    else if (match_pat(in_sizes, ALPHA_E, ALPHA_IDX_POS, 2, 4)) { in_mode = 1; alpha = true; }
    if (in_mode == -2) return;

    const void* p[20];
    if (alpha) { for (int i = 0; i < 20; i++) p[ALPHA_TO_SIG[i]] = d_in[i]; }
    else       { for (int i = 0; i < 20; i++) p[i] = d_in[i]; }

    long long osz = (long long)out_size;
    const long long OE = (long long)M_TOK * V;
    int out_mode; int lm_rows;
    if      (osz == OE)     { out_mode = -1; lm_rows = M_TOK; }
    else if (osz == 4 * OE) { out_mode = 0;  lm_rows = M_TOK; }
    else if (osz == 2 * OE) { out_mode = 1;  lm_rows = M_TOK; }
    else                    { out_mode = 0;  lm_rows = 0;     }

    const int* idx = (const int*)p[0];

    flags_kernel<<<1, 256>>>(p[1], in_mode, out_mode);
    long long off[19];
    {
        long long o = 0;
        for (int i = 0; i < 19; i++) {
            off[i] = o;
            convert_kernel<<<(FSIZES[i] + 255) / 256, 256>>>(p[i + 1], o, FSIZES[i], FROUND[i]);
            o += FSIZES[i];
        }
    }
    const long long oTok = off[0],  oPos = off[1];
    const long long oL1g = off[2],  oL1b = off[3];
    const long long oWq = off[4], oWk = off[5], oWv = off[6], oWo = off[7];
    const long long oWob = off[8], oL2g = off[9], oL2b = off[10];
    const long long oW1 = off[11], oB1 = off[12], oW2 = off[13], oB2 = off[14];
    const long long oLfg = off[15], oLfb = off[16], oLmw = off[17], oLmb = off[18];
    const long long oQKVW = WBUF_ORIG;

    pack_qkv<<<(NL * C * C3 + 255) / 256, 256>>>(oWq, oWk, oWv, oQKVW);

    embed_kernel<<<M_TOK, C>>>(idx, oTok, oPos);

    dim3 gQKV(C3 / 128, M_TOK / 128);   // (9, 64)
    dim3 gC  (C  / 128, M_TOK / 128);
    dim3 gF  (FF / 128, M_TOK / 128);
    dim3 gV  (V  / 128, M_TOK / 128);

    // scratch selectors: 0=x 1=h 5=att 6=mlp 7=qkv
    for (int l = 0; l < NL; l++) {
        long long qkv_l = oQKVW + (long long)l * C * C3;
        long long wo_l  = oWo + (long long)l * C * C;
        long long wob_l = oWob + (long long)l * C;
        long long w1_l  = oW1 + (long long)l * C * FF;
        long long b1_l  = oB1 + (long long)l * FF;
        long long w2_l  = oW2 + (long long)l * FF * C;
        long long b2_l  = oB2 + (long long)l * C;

        ln_kernel<<<M_TOK, 128>>>(0, oL1g + l * C, oL1b + l * C, 1, 1);
        mma_gemm<false,false,false,false,false><<<gQKV, 256>>>(1, qkv_l, 0, 7, nullptr, M_TOK, C3, C, M_TOK);
        flash_attn<<<BB * HN * 8, 256>>>();
        mma_gemm<true,false,true,false,false><<<gC, 256>>>(5, wo_l, wob_l, 0, nullptr, M_TOK, C, C, M_TOK);
        ln_kernel<<<M_TOK, 128>>>(0, oL2g + l * C, oL2b + l * C, 1, 1);
        mma_gemm<true,true,false,true,false><<<gF, 256>>>(1, w1_l, b1_l, 6, nullptr, M_TOK, FF, C, M_TOK);
        mma_gemm<true,false,true,false,false><<<gC, 256>>>(6, w2_l, b2_l, 0, nullptr, M_TOK, C, FF, M_TOK);
    }

    ln_kernel<<<M_TOK, 128>>>(0, oLfg, oLfb, 1, 1);
    mma_gemm<true,false,false,false,true><<<gV, 256>>>(1, oLmw, oLmb, 0, d_out, M_TOK, V, C, lm_rows);
}